// round 4
// baseline (speedup 1.0000x reference)
#include <cuda_runtime.h>
#include <cstdint>
#include <cstddef>

#define BB 64
#define TT 512
#define EE 300
#define HH 1024
#define GG 3072   // 3*HH
#define OO 5

#define NB 128    // blocks in persistent recurrent kernel (1 per SM)
#define JPB 8     // HH / NB hidden units per block
#define THR 512   // threads in k_rnn: 16 warps = 16-way k-split

// ---------------- device scratch ----------------
__device__ float g_gx[(size_t)TT * GG * BB];   // [t][g][b]
__device__ float g_WT[EE * GG];                // W_ih transposed: [e][g]
__device__ float g_h[2][HH * BB];              // hidden double buffer, [j][b]
__device__ unsigned g_flags[NB * 32];          // per-block barrier flags, 128B stride

// ---------------- f32x2 helpers (sm_103a packed fp32) ----------------
__device__ __forceinline__ void fma2(uint64_t& a, uint64_t b, uint64_t c) {
    asm("fma.rn.f32x2 %0, %1, %2, %0;" : "+l"(a) : "l"(b), "l"(c));
}
__device__ __forceinline__ uint64_t dup2(float x) {
    uint64_t r; asm("mov.b64 %0, {%1, %1};" : "=l"(r) : "f"(x)); return r;
}
__device__ __forceinline__ void unpk(uint64_t v, float& lo, float& hi) {
    asm("mov.b64 {%0, %1}, %2;" : "=f"(lo), "=f"(hi) : "l"(v));
}

// ---------------- tiny helpers ----------------
__global__ void k_reset() { if (threadIdx.x < NB) g_flags[threadIdx.x * 32] = 0u; }

__global__ void k_transpose(const float* __restrict__ Wih) {
    int i = blockIdx.x * blockDim.x + threadIdx.x;
    if (i < EE * GG) {
        int e = i / GG, g = i - e * GG;
        g_WT[i] = Wih[(size_t)g * EE + e];
    }
}

// ---------------- kernel A: gx[t][g][b] ----------------
__global__ void __launch_bounds__(256) k_gx(const int* __restrict__ x,
                                            const float* __restrict__ emb,
                                            const float* __restrict__ bih) {
    extern __shared__ float sm[];
    float* embS = sm;            // [e][b]
    float* Wt   = sm + EE * BB;  // [e][64] current g-tile

    const int t   = blockIdx.x;
    const int tid = threadIdx.x;

    for (int i = tid; i < BB * EE; i += 256) {
        int b = i / EE, e = i - b * EE;
        embS[e * BB + b] = emb[(size_t)x[b * TT + t] * EE + e];
    }

    const int bg = tid & 31;
    const int gy = tid >> 5;

    for (int gt = 0; gt < GG / 64; gt++) {
        __syncthreads();
        for (int i = tid; i < EE * 64; i += 256) {
            int e = i >> 6, g = i & 63;
            Wt[i] = g_WT[e * GG + gt * 64 + g];
        }
        __syncthreads();

        uint64_t a0[4], a1[4];
        uint64_t z0 = dup2(0.f);
#pragma unroll
        for (int p = 0; p < 4; p++) { a0[p] = z0; a1[p] = z0; }

#pragma unroll 4
        for (int e = 0; e < EE; e++) {
            float2 eb = *(float2*)&embS[e * BB + bg * 2];
            uint64_t e0 = dup2(eb.x), e1 = dup2(eb.y);
            const uint64_t* wr = (const uint64_t*)&Wt[e * 64 + gy * 8];
#pragma unroll
            for (int p = 0; p < 4; p++) {
                uint64_t w = wr[p];
                fma2(a0[p], w, e0);
                fma2(a1[p], w, e1);
            }
        }
#pragma unroll
        for (int p = 0; p < 4; p++) {
            int j = gt * 64 + gy * 8 + 2 * p;
            float l0, h0, l1, h1;
            unpk(a0[p], l0, h0);
            unpk(a1[p], l1, h1);
            float bj = bih[j], bk = bih[j + 1];
            size_t base = ((size_t)t * GG + j) * BB + bg * 2;
            g_gx[base]          = l0 + bj;
            g_gx[base + 1]      = l1 + bj;
            g_gx[base + BB]     = h0 + bk;
            g_gx[base + BB + 1] = h1 + bk;
        }
    }
}

// ---------------- flag-based grid barrier ----------------
__device__ __forceinline__ void gridbar(unsigned tgt) {
    __threadfence();
    __syncthreads();
    if (threadIdx.x == 0)
        asm volatile("st.global.release.gpu.u32 [%0], %1;"
                     :: "l"(&g_flags[blockIdx.x * 32]), "r"(tgt) : "memory");
    if (threadIdx.x < NB) {
        unsigned v;
        do {
            asm volatile("ld.global.acquire.gpu.u32 %0, [%1];"
                         : "=r"(v) : "l"(&g_flags[threadIdx.x * 32]) : "memory");
        } while (v < tgt);
    }
    __syncthreads();
}

__device__ __forceinline__ float sigf(float v) { return 1.0f / (1.0f + expf(-v)); }

// ---------------- kernel B: persistent GRU recurrence ----------------
// 512 thr = 16 warps. Warp w owns k in [w*64, w*64+64).
// Lane: bg = lane&7 (8 b's), jg = lane>>3 (j-pair).
// h read DIRECTLY from L2 via __ldcg (coalescer dedups the 4 jp-lanes sharing
// each h[k][b]); smem only holds W (resident all 512 steps) + reduction scratch.
__global__ void __launch_bounds__(THR, 1) k_rnn(const float* __restrict__ Whh,
                                                const float* __restrict__ bhh) {
    extern __shared__ float sm[];
    float* Wsm     = sm;                     // [3][1024][8]  = 24576 floats (96 KB)
    uint64_t* part = (uint64_t*)(sm + 24576);// 12288 u64 (96 KB)

    const int tid  = threadIdx.x;
    const int w    = tid >> 5, lane = tid & 31;
    const int bg   = lane & 7, jg = lane >> 3;
    const int jbase = blockIdx.x * JPB;

    // load W_hh slice once: Wsm[(g*1024+k)*8 + jl]
    for (int i = tid; i < 3 * HH * JPB; i += THR) {
        int jl = i & 7, k = (i >> 3) & (HH - 1), g = i >> 13;
        Wsm[i] = Whh[((size_t)(g * HH + jbase + jl)) * HH + k];
    }

    // consumer role (tid < 256): handles (j-pair cjg, batch cb)
    const int cjg = (tid >> 6) & 3;
    const int cb  = tid & 63;
    const int cbg = cb >> 3, cbi = cb & 7;
    const int j0 = jbase + cjg * 2, j1 = j0 + 1;
    const float br0 = bhh[j0],          br1 = bhh[j1];
    const float bz0 = bhh[HH + j0],     bz1 = bhh[HH + j1];
    const float bn0 = bhh[2 * HH + j0], bn1 = bhh[2 * HH + j1];
    const bool consumer = (tid < 256);

    // zero h buffer 0 (our slice)
    for (int i = tid; i < JPB * BB; i += THR)
        __stcg(&g_h[0][jbase * BB + i], 0.f);

    gridbar(1);

    const uint64_t zz = dup2(0.f);
    const int kb = w * 64;

    for (int t = 0; t < TT; t++) {
        const float* hin  = g_h[t & 1];
        float*       hout = g_h[(t + 1) & 1];

        // prefetch gate operands (consumers only; warp-uniform branch)
        float xr0, xr1, xz0, xz1, xn0, xn1, hp0, hp1;
        if (consumer) {
            const float* gxt = g_gx + (size_t)t * GG * BB;
            xr0 = __ldcg(&gxt[(0 * HH + j0) * BB + cb]);
            xr1 = __ldcg(&gxt[(0 * HH + j1) * BB + cb]);
            xz0 = __ldcg(&gxt[(1 * HH + j0) * BB + cb]);
            xz1 = __ldcg(&gxt[(1 * HH + j1) * BB + cb]);
            xn0 = __ldcg(&gxt[(2 * HH + j0) * BB + cb]);
            xn1 = __ldcg(&gxt[(2 * HH + j1) * BB + cb]);
            hp0 = __ldcg(&hin[j0 * BB + cb]);
            hp1 = __ldcg(&hin[j1 * BB + cb]);
        }

        uint64_t aR[8], aZ[8], aN[8];
#pragma unroll
        for (int b = 0; b < 8; b++) { aR[b] = zz; aZ[b] = zz; aN[b] = zz; }

        // ---- k-loop: h straight from L2, weights from smem ----
        const float* hk = hin + (size_t)kb * BB + bg * 8;
#pragma unroll 4
        for (int k2 = 0; k2 < 64; k2++) {
            const int k = kb + k2;
            float4 ha = __ldcg((const float4*)(hk + k2 * BB));
            float4 hc = __ldcg((const float4*)(hk + k2 * BB + 4));
            uint64_t wr  = *(const uint64_t*)&Wsm[(0 * HH + k) * 8 + jg * 2];
            uint64_t wz2 = *(const uint64_t*)&Wsm[(1 * HH + k) * 8 + jg * 2];
            uint64_t wn2 = *(const uint64_t*)&Wsm[(2 * HH + k) * 8 + jg * 2];
            uint64_t d0 = dup2(ha.x), d1 = dup2(ha.y), d2 = dup2(ha.z), d3 = dup2(ha.w);
            uint64_t d4 = dup2(hc.x), d5 = dup2(hc.y), d6 = dup2(hc.z), d7 = dup2(hc.w);
            fma2(aR[0], wr, d0);  fma2(aR[1], wr, d1);  fma2(aR[2], wr, d2);  fma2(aR[3], wr, d3);
            fma2(aR[4], wr, d4);  fma2(aR[5], wr, d5);  fma2(aR[6], wr, d6);  fma2(aR[7], wr, d7);
            fma2(aZ[0], wz2, d0); fma2(aZ[1], wz2, d1); fma2(aZ[2], wz2, d2); fma2(aZ[3], wz2, d3);
            fma2(aZ[4], wz2, d4); fma2(aZ[5], wz2, d5); fma2(aZ[6], wz2, d6); fma2(aZ[7], wz2, d7);
            fma2(aN[0], wn2, d0); fma2(aN[1], wn2, d1); fma2(aN[2], wn2, d2); fma2(aN[3], wn2, d3);
            fma2(aN[4], wn2, d4); fma2(aN[5], wn2, d5); fma2(aN[6], wn2, d6); fma2(aN[7], wn2, d7);
        }

        // ---- 16-way k-split reduction via smem ----
#pragma unroll
        for (int bi = 0; bi < 8; bi++) {
            int col = ((jg * 8 + bg) + bi * 8) & 31;   // swizzle: conflict-bounded
            part[(w * 3 + 0) * 256 + bi * 32 + col] = aR[bi];
            part[(w * 3 + 1) * 256 + bi * 32 + col] = aZ[bi];
            part[(w * 3 + 2) * 256 + bi * 32 + col] = aN[bi];
        }
        __syncthreads();

        if (consumer) {
            float sR0 = 0.f, sR1 = 0.f, sZ0 = 0.f, sZ1 = 0.f, sN0 = 0.f, sN1 = 0.f;
            const int ccol = ((cjg * 8 + cbg) + cbi * 8) & 31;
#pragma unroll
            for (int s = 0; s < 16; s++) {
                float2 vr = *(const float2*)&part[(s * 3 + 0) * 256 + cbi * 32 + ccol];
                float2 vz = *(const float2*)&part[(s * 3 + 1) * 256 + cbi * 32 + ccol];
                float2 vn = *(const float2*)&part[(s * 3 + 2) * 256 + cbi * 32 + ccol];
                sR0 += vr.x; sR1 += vr.y;
                sZ0 += vz.x; sZ1 += vz.y;
                sN0 += vn.x; sN1 += vn.y;
            }
            float r, z, n;
            r = sigf(xr0 + sR0 + br0);
            z = sigf(xz0 + sZ0 + bz0);
            n = tanhf(xn0 + r * (sN0 + bn0));
            __stcg(&hout[j0 * BB + cb], (1.f - z) * n + z * hp0);
            r = sigf(xr1 + sR1 + br1);
            z = sigf(xz1 + sZ1 + bz1);
            n = tanhf(xn1 + r * (sN1 + bn1));
            __stcg(&hout[j1 * BB + cb], (1.f - z) * n + z * hp1);
        }

        gridbar((unsigned)(t + 2));
    }
}

// ---------------- kernel C: FC ----------------
__global__ void k_fc(const float* __restrict__ Wfc, const float* __restrict__ bfc,
                     float* __restrict__ out) {
    int tid = threadIdx.x;
    if (tid >= BB * OO) return;
    int b = tid & 63, o = tid >> 6;
    const float* h = g_h[0];   // TT even -> final state in buffer 0
    float a0 = 0.f, a1 = 0.f, a2 = 0.f, a3 = 0.f;
    for (int j = 0; j < HH; j += 4) {
        a0 += h[(j + 0) * BB + b] * Wfc[o * HH + j + 0];
        a1 += h[(j + 1) * BB + b] * Wfc[o * HH + j + 1];
        a2 += h[(j + 2) * BB + b] * Wfc[o * HH + j + 2];
        a3 += h[(j + 3) * BB + b] * Wfc[o * HH + j + 3];
    }
    out[b * OO + o] = a0 + a1 + a2 + a3 + bfc[o];
}

// ---------------- entry ----------------
extern "C" void kernel_launch(void* const* d_in, const int* in_sizes, int n_in,
                              void* d_out, int out_size) {
    const int*   x   = (const int*)d_in[0];
    const float* emb = (const float*)d_in[1];
    const float* Wih = (const float*)d_in[2];
    const float* Whh = (const float*)d_in[3];
    const float* bih = (const float*)d_in[4];
    const float* bhh = (const float*)d_in[5];
    const float* Wfc = (const float*)d_in[6];
    const float* bfc = (const float*)d_in[7];
    float* out = (float*)d_out;

    const int smemA = 2 * EE * BB * (int)sizeof(float);          // 153.6 KB
    const int smemB = (24576 + 24576) * (int)sizeof(float);      // 192 KB
    cudaFuncSetAttribute(k_gx,  cudaFuncAttributeMaxDynamicSharedMemorySize, smemA);
    cudaFuncSetAttribute(k_rnn, cudaFuncAttributeMaxDynamicSharedMemorySize, smemB);

    k_reset<<<1, 128>>>();
    k_transpose<<<(EE * GG + 255) / 256, 256>>>(Wih);
    k_gx<<<TT, 256, smemA>>>(x, emb, bih);
    k_rnn<<<NB, THR, smemB>>>(Whh, bhh);
    k_fc<<<1, 512>>>(Wfc, bfc, out);
}

// round 6
// speedup vs baseline: 1.0693x; 1.0693x over previous
#include <cuda_runtime.h>
#include <cstdint>
#include <cstddef>

#define BB 64
#define TT 512
#define EE 300
#define HH 1024
#define GG 3072   // 3*HH
#define OO 5

#define NB 128    // blocks in persistent recurrent kernel (1 per SM)
#define JPB 8     // HH / NB hidden units per block
#define THR 512   // threads in k_rnn: 16 warps = 16-way k-split

// ---------------- device scratch ----------------
__device__ float g_gx[(size_t)TT * GG * BB];   // [t][g][b]
__device__ float g_WT[EE * GG];                // W_ih transposed: [e][g]
__device__ float g_h[4][HH * BB];              // hidden 4-deep ring, [j][b]
__device__ unsigned g_flags[NB * 32];          // flag[p*32] = completed steps + 1

// ---------------- f32x2 helpers (sm_103a packed fp32) ----------------
__device__ __forceinline__ void fma2(uint64_t& a, uint64_t b, uint64_t c) {
    asm("fma.rn.f32x2 %0, %1, %2, %0;" : "+l"(a) : "l"(b), "l"(c));
}
__device__ __forceinline__ uint64_t dup2(float x) {
    uint64_t r; asm("mov.b64 %0, {%1, %1};" : "=l"(r) : "f"(x)); return r;
}
__device__ __forceinline__ void unpk(uint64_t v, float& lo, float& hi) {
    asm("mov.b64 {%0, %1}, %2;" : "=f"(lo), "=f"(hi) : "l"(v));
}
__device__ __forceinline__ unsigned ldacq(const unsigned* p) {
    unsigned v;
    asm volatile("ld.global.acquire.gpu.u32 %0, [%1];" : "=r"(v) : "l"(p) : "memory");
    return v;
}
__device__ __forceinline__ void strel(unsigned* p, unsigned v) {
    asm volatile("st.global.release.gpu.u32 [%0], %1;" :: "l"(p), "r"(v) : "memory");
}

// ---------------- tiny helpers ----------------
__global__ void k_reset() { if (threadIdx.x < NB) g_flags[threadIdx.x * 32] = 0u; }

__global__ void k_transpose(const float* __restrict__ Wih) {
    int i = blockIdx.x * blockDim.x + threadIdx.x;
    if (i < EE * GG) {
        int e = i / GG, g = i - e * GG;
        g_WT[i] = Wih[(size_t)g * EE + e];
    }
}

// ---------------- kernel A: gx[t][g][b] ----------------
__global__ void __launch_bounds__(256) k_gx(const int* __restrict__ x,
                                            const float* __restrict__ emb,
                                            const float* __restrict__ bih) {
    extern __shared__ float sm[];
    float* embS = sm;            // [e][b]
    float* Wt   = sm + EE * BB;  // [e][64] current g-tile

    const int t   = blockIdx.x;
    const int tid = threadIdx.x;

    for (int i = tid; i < BB * EE; i += 256) {
        int b = i / EE, e = i - b * EE;
        embS[e * BB + b] = emb[(size_t)x[b * TT + t] * EE + e];
    }

    const int bg = tid & 31;
    const int gy = tid >> 5;

    for (int gt = 0; gt < GG / 64; gt++) {
        __syncthreads();
        for (int i = tid; i < EE * 64; i += 256) {
            int e = i >> 6, g = i & 63;
            Wt[i] = g_WT[e * GG + gt * 64 + g];
        }
        __syncthreads();

        uint64_t a0[4], a1[4];
        uint64_t z0 = dup2(0.f);
#pragma unroll
        for (int p = 0; p < 4; p++) { a0[p] = z0; a1[p] = z0; }

#pragma unroll 4
        for (int e = 0; e < EE; e++) {
            float2 eb = *(float2*)&embS[e * BB + bg * 2];
            uint64_t e0 = dup2(eb.x), e1 = dup2(eb.y);
            // W via 2x LDS.128 (broadcast) instead of 4x LDS.64
            ulonglong2 wv0 = *(const ulonglong2*)&Wt[e * 64 + gy * 8];
            ulonglong2 wv1 = *(const ulonglong2*)&Wt[e * 64 + gy * 8 + 4];
            fma2(a0[0], wv0.x, e0); fma2(a1[0], wv0.x, e1);
            fma2(a0[1], wv0.y, e0); fma2(a1[1], wv0.y, e1);
            fma2(a0[2], wv1.x, e0); fma2(a1[2], wv1.x, e1);
            fma2(a0[3], wv1.y, e0); fma2(a1[3], wv1.y, e1);
        }
#pragma unroll
        for (int p = 0; p < 4; p++) {
            int j = gt * 64 + gy * 8 + 2 * p;
            float l0, h0, l1, h1;
            unpk(a0[p], l0, h0);
            unpk(a1[p], l1, h1);
            float bj = bih[j], bk = bih[j + 1];
            size_t base = ((size_t)t * GG + j) * BB + bg * 2;
            g_gx[base]          = l0 + bj;
            g_gx[base + 1]      = l1 + bj;
            g_gx[base + BB]     = h0 + bk;
            g_gx[base + BB + 1] = h1 + bk;
        }
    }
}

__device__ __forceinline__ float sigf(float v) { return 1.0f / (1.0f + expf(-v)); }

// ---------------- kernel B: persistent GRU recurrence, flag-pipelined ----------------
// 16 warps; warp w owns k in [64w, 64w+64), produced by blocks 8w..8w+7.
// No global barrier: each warp waits only on its 8 producers' flags. h is a
// 4-deep ring; writer gate (all flags >= t-1) protects WAR, idle in steady state.
__global__ void __launch_bounds__(THR, 1) k_rnn(const float* __restrict__ Whh,
                                                const float* __restrict__ bhh) {
    extern __shared__ float sm[];
    float* Wsm     = sm;                      // [3][1024][8] = 24576 floats (96 KB)
    uint64_t* part = (uint64_t*)(sm + 24576); // 12288 u64 (96 KB)

    const int tid  = threadIdx.x;
    const int w    = tid >> 5, lane = tid & 31;
    const int bg   = lane & 7, jg = lane >> 3;
    const int jbase = blockIdx.x * JPB;

    // load W_hh slice once: Wsm[(g*1024+k)*8 + jl]
    for (int i = tid; i < 3 * HH * JPB; i += THR) {
        int jl = i & 7, k = (i >> 3) & (HH - 1), g = i >> 13;
        Wsm[i] = Whh[((size_t)(g * HH + jbase + jl)) * HH + k];
    }

    // consumer role: one (j, b) per thread
    const int cj  = tid >> 6;           // 0..7
    const int cb  = tid & 63;
    const int cjg = cj >> 1, cpar = cj & 1;
    const int cbg = cb >> 3, cbi = cb & 7;
    const int jglob = jbase + cj;
    const float br = bhh[jglob], bz = bhh[HH + jglob], bn = bhh[2 * HH + jglob];
    const int ccol = ((cjg * 8 + cbg) + cbi * 8) & 31;
    const int cfl  = (cbi * 32 + ccol) * 2 + cpar;  // float offset inside a [w][g] tile

    // zero own slice of h_0 (ring slot 0), then publish flag = 1
    for (int i = tid; i < JPB * BB; i += THR)
        __stcg(&g_h[0][jbase * BB + i], 0.f);
    __threadfence();
    __syncthreads();
    if (tid == 0) strel(&g_flags[blockIdx.x * 32], 1u);

    const uint64_t zz = dup2(0.f);
    const int kb = w * 64;
    const unsigned* pflag = &g_flags[(8 * w + (lane & 7)) * 32];  // producer flag (lane<8)

    for (int t = 0; t < TT; t++) {
        const float* hin  = g_h[t & 3];
        float*       hout = g_h[(t + 1) & 3];

        // gate-operand prefetch (own slice / static gx: no cross-block dependency)
        const float* gxt = g_gx + (size_t)t * GG * BB;
        float xr = __ldcg(&gxt[(0 * HH + jglob) * BB + cb]);
        float xz = __ldcg(&gxt[(1 * HH + jglob) * BB + cb]);
        float xn = __ldcg(&gxt[(2 * HH + jglob) * BB + cb]);
        float hp = __ldcg(&hin[jglob * BB + cb]);   // own block produced this

        // wait for the 8 producers of this warp's k-range to publish h_t
        if (lane < 8) {
            while (ldacq(pflag) < (unsigned)(t + 1)) { }
        }
        __syncwarp();

        uint64_t aR[8], aZ[8], aN[8];
#pragma unroll
        for (int b = 0; b < 8; b++) { aR[b] = zz; aZ[b] = zz; aN[b] = zz; }

        // ---- k-loop: h straight from L2, weights from smem ----
        const float* hk = hin + (size_t)kb * BB + bg * 8;
#pragma unroll 4
        for (int k2 = 0; k2 < 64; k2++) {
            const int k = kb + k2;
            float4 ha = __ldcg((const float4*)(hk + k2 * BB));
            float4 hc = __ldcg((const float4*)(hk + k2 * BB + 4));
            uint64_t wr  = *(const uint64_t*)&Wsm[(0 * HH + k) * 8 + jg * 2];
            uint64_t wz2 = *(const uint64_t*)&Wsm[(1 * HH + k) * 8 + jg * 2];
            uint64_t wn2 = *(const uint64_t*)&Wsm[(2 * HH + k) * 8 + jg * 2];
            uint64_t d0 = dup2(ha.x), d1 = dup2(ha.y), d2 = dup2(ha.z), d3 = dup2(ha.w);
            uint64_t d4 = dup2(hc.x), d5 = dup2(hc.y), d6 = dup2(hc.z), d7 = dup2(hc.w);
            fma2(aR[0], wr, d0);  fma2(aR[1], wr, d1);  fma2(aR[2], wr, d2);  fma2(aR[3], wr, d3);
            fma2(aR[4], wr, d4);  fma2(aR[5], wr, d5);  fma2(aR[6], wr, d6);  fma2(aR[7], wr, d7);
            fma2(aZ[0], wz2, d0); fma2(aZ[1], wz2, d1); fma2(aZ[2], wz2, d2); fma2(aZ[3], wz2, d3);
            fma2(aZ[4], wz2, d4); fma2(aZ[5], wz2, d5); fma2(aZ[6], wz2, d6); fma2(aZ[7], wz2, d7);
            fma2(aN[0], wn2, d0); fma2(aN[1], wn2, d1); fma2(aN[2], wn2, d2); fma2(aN[3], wn2, d3);
            fma2(aN[4], wn2, d4); fma2(aN[5], wn2, d5); fma2(aN[6], wn2, d6); fma2(aN[7], wn2, d7);
        }

        // ---- store partials ----
#pragma unroll
        for (int bi = 0; bi < 8; bi++) {
            int col = ((jg * 8 + bg) + bi * 8) & 31;
            part[(w * 3 + 0) * 256 + bi * 32 + col] = aR[bi];
            part[(w * 3 + 1) * 256 + bi * 32 + col] = aZ[bi];
            part[(w * 3 + 2) * 256 + bi * 32 + col] = aN[bi];
        }

        // writer gate: h_{t+1} overwrites h_{t-3}; need all blocks past step t-3.
        // Steady-state no-op (skew <= 3 is impossible without this being true).
        if (t >= 3 && tid < NB) {
            const unsigned* fp = &g_flags[tid * 32];
            while (ldacq(fp) < (unsigned)(t - 1)) { }
        }
        __syncthreads();

        // ---- consume: 16-way reduction + gates, one (j,b) per thread ----
        {
            const float* pf = (const float*)part;
            float sR = 0.f, sZ = 0.f, sN = 0.f;
#pragma unroll
            for (int s = 0; s < 16; s++) {
                sR += pf[s * 1536 + 0 * 512 + cfl];
                sZ += pf[s * 1536 + 1 * 512 + cfl];
                sN += pf[s * 1536 + 2 * 512 + cfl];
            }
            float r = sigf(xr + sR + br);
            float z = sigf(xz + sZ + bz);
            float n = tanhf(xn + r * (sN + bn));
            __stcg(&hout[jglob * BB + cb], (1.f - z) * n + z * hp);
        }

        __threadfence();
        __syncthreads();   // all h stores done + part reads done before next step
        if (tid == 0) strel(&g_flags[blockIdx.x * 32], (unsigned)(t + 2));
    }
}

// ---------------- kernel C: FC ----------------
__global__ void k_fc(const float* __restrict__ Wfc, const float* __restrict__ bfc,
                     float* __restrict__ out) {
    int tid = threadIdx.x;
    if (tid >= BB * OO) return;
    int b = tid & 63, o = tid >> 6;
    const float* h = g_h[0];   // h_512 lives in ring slot 512 & 3 = 0
    float a0 = 0.f, a1 = 0.f, a2 = 0.f, a3 = 0.f;
    for (int j = 0; j < HH; j += 4) {
        a0 += h[(j + 0) * BB + b] * Wfc[o * HH + j + 0];
        a1 += h[(j + 1) * BB + b] * Wfc[o * HH + j + 1];
        a2 += h[(j + 2) * BB + b] * Wfc[o * HH + j + 2];
        a3 += h[(j + 3) * BB + b] * Wfc[o * HH + j + 3];
    }
    out[b * OO + o] = a0 + a1 + a2 + a3 + bfc[o];
}

// ---------------- entry ----------------
extern "C" void kernel_launch(void* const* d_in, const int* in_sizes, int n_in,
                              void* d_out, int out_size) {
    const int*   x   = (const int*)d_in[0];
    const float* emb = (const float*)d_in[1];
    const float* Wih = (const float*)d_in[2];
    const float* Whh = (const float*)d_in[3];
    const float* bih = (const float*)d_in[4];
    const float* bhh = (const float*)d_in[5];
    const float* Wfc = (const float*)d_in[6];
    const float* bfc = (const float*)d_in[7];
    float* out = (float*)d_out;

    const int smemA = 2 * EE * BB * (int)sizeof(float);          // 153.6 KB
    const int smemB = (24576 + 24576) * (int)sizeof(float);      // 192 KB
    cudaFuncSetAttribute(k_gx,  cudaFuncAttributeMaxDynamicSharedMemorySize, smemA);
    cudaFuncSetAttribute(k_rnn, cudaFuncAttributeMaxDynamicSharedMemorySize, smemB);

    k_reset<<<1, 128>>>();
    k_transpose<<<(EE * GG + 255) / 256, 256>>>(Wih);
    k_gx<<<TT, 256, smemA>>>(x, emb, bih);
    k_rnn<<<NB, THR, smemB>>>(Whh, bhh);
    k_fc<<<1, 512>>>(Wfc, bfc, out);
}

// round 8
// speedup vs baseline: 1.0758x; 1.0061x over previous
#include <cuda_runtime.h>
#include <cstdint>
#include <cstddef>

#define BB 64
#define TT 512
#define EE 300
#define HH 1024
#define GG 3072   // 3*HH
#define OO 5

#define NB 128    // blocks in persistent recurrent kernel (1 per SM)
#define JPB 8     // HH / NB hidden units per block
#define THR 512   // threads in k_rnn: 16 warps = 16-way k-split

// ---------------- device scratch ----------------
__device__ float g_gx[(size_t)TT * GG * BB];   // [t][g][b]
__device__ float g_WT[EE * GG];                // W_ih transposed: [e][g]
__device__ float g_h[4][HH * BB];              // hidden 4-deep ring, [j][b]
__device__ unsigned g_flags[NB * 32];          // flag[p*32] = completed steps + 1

// ---------------- f32x2 helpers (sm_103a packed fp32) ----------------
__device__ __forceinline__ void fma2(uint64_t& a, uint64_t b, uint64_t c) {
    asm("fma.rn.f32x2 %0, %1, %2, %0;" : "+l"(a) : "l"(b), "l"(c));
}
__device__ __forceinline__ uint64_t dup2(float x) {
    uint64_t r; asm("mov.b64 %0, {%1, %1};" : "=l"(r) : "f"(x)); return r;
}
__device__ __forceinline__ void unpk(uint64_t v, float& lo, float& hi) {
    asm("mov.b64 {%0, %1}, %2;" : "=f"(lo), "=f"(hi) : "l"(v));
}
__device__ __forceinline__ unsigned ldacq(const unsigned* p) {
    unsigned v;
    asm volatile("ld.global.acquire.gpu.u32 %0, [%1];" : "=r"(v) : "l"(p) : "memory");
    return v;
}
__device__ __forceinline__ void strel(unsigned* p, unsigned v) {
    asm volatile("st.global.release.gpu.u32 [%0], %1;" :: "l"(p), "r"(v) : "memory");
}

// ---------------- tiny helpers ----------------
__global__ void k_reset() { if (threadIdx.x < NB) g_flags[threadIdx.x * 32] = 0u; }

__global__ void k_transpose(const float* __restrict__ Wih) {
    int i = blockIdx.x * blockDim.x + threadIdx.x;
    if (i < EE * GG) {
        int e = i / GG, g = i - e * GG;
        g_WT[i] = Wih[(size_t)g * EE + e];
    }
}

// ---------------- kernel A: gx[t][g][b] ----------------
__global__ void __launch_bounds__(256) k_gx(const int* __restrict__ x,
                                            const float* __restrict__ emb,
                                            const float* __restrict__ bih) {
    extern __shared__ float sm[];
    float* embS = sm;            // [e][b]
    float* Wt   = sm + EE * BB;  // [e][64] current g-tile

    const int t   = blockIdx.x;
    const int tid = threadIdx.x;

    for (int i = tid; i < BB * EE; i += 256) {
        int b = i / EE, e = i - b * EE;
        embS[e * BB + b] = emb[(size_t)x[b * TT + t] * EE + e];
    }

    const int bg = tid & 31;
    const int gy = tid >> 5;

    for (int gt = 0; gt < GG / 64; gt++) {
        __syncthreads();
        for (int i = tid; i < EE * 64; i += 256) {
            int e = i >> 6, g = i & 63;
            Wt[i] = g_WT[e * GG + gt * 64 + g];
        }
        __syncthreads();

        uint64_t a0[4], a1[4];
        uint64_t z0 = dup2(0.f);
#pragma unroll
        for (int p = 0; p < 4; p++) { a0[p] = z0; a1[p] = z0; }

#pragma unroll 4
        for (int e = 0; e < EE; e++) {
            float2 eb = *(float2*)&embS[e * BB + bg * 2];
            uint64_t e0 = dup2(eb.x), e1 = dup2(eb.y);
            // W via 2x LDS.128 (broadcast) instead of 4x LDS.64
            ulonglong2 wv0 = *(const ulonglong2*)&Wt[e * 64 + gy * 8];
            ulonglong2 wv1 = *(const ulonglong2*)&Wt[e * 64 + gy * 8 + 4];
            fma2(a0[0], wv0.x, e0); fma2(a1[0], wv0.x, e1);
            fma2(a0[1], wv0.y, e0); fma2(a1[1], wv0.y, e1);
            fma2(a0[2], wv1.x, e0); fma2(a1[2], wv1.x, e1);
            fma2(a0[3], wv1.y, e0); fma2(a1[3], wv1.y, e1);
        }
#pragma unroll
        for (int p = 0; p < 4; p++) {
            int j = gt * 64 + gy * 8 + 2 * p;
            float l0, h0, l1, h1;
            unpk(a0[p], l0, h0);
            unpk(a1[p], l1, h1);
            float bj = bih[j], bk = bih[j + 1];
            size_t base = ((size_t)t * GG + j) * BB + bg * 2;
            g_gx[base]          = l0 + bj;
            g_gx[base + 1]      = l1 + bj;
            g_gx[base + BB]     = h0 + bk;
            g_gx[base + BB + 1] = h1 + bk;
        }
    }
}

__device__ __forceinline__ float sigf(float v) { return 1.0f / (1.0f + expf(-v)); }

// ---------------- kernel B: persistent GRU recurrence, flag-pipelined ----------------
// 16 warps; warp w owns k in [64w, 64w+64), produced by blocks 8w..8w+7.
// No global barrier: each warp waits only on its 8 producers' flags. h is a
// 4-deep ring; writer gate (all flags >= t-1) protects WAR, idle in steady state.
__global__ void __launch_bounds__(THR, 1) k_rnn(const float* __restrict__ Whh,
                                                const float* __restrict__ bhh) {
    extern __shared__ float sm[];
    float* Wsm     = sm;                      // [3][1024][8] = 24576 floats (96 KB)
    uint64_t* part = (uint64_t*)(sm + 24576); // 12288 u64 (96 KB)

    const int tid  = threadIdx.x;
    const int w    = tid >> 5, lane = tid & 31;
    const int bg   = lane & 7, jg = lane >> 3;
    const int jbase = blockIdx.x * JPB;

    // load W_hh slice once: Wsm[(g*1024+k)*8 + jl]
    for (int i = tid; i < 3 * HH * JPB; i += THR) {
        int jl = i & 7, k = (i >> 3) & (HH - 1), g = i >> 13;
        Wsm[i] = Whh[((size_t)(g * HH + jbase + jl)) * HH + k];
    }

    // consumer role: one (j, b) per thread
    const int cj  = tid >> 6;           // 0..7
    const int cb  = tid & 63;
    const int cjg = cj >> 1, cpar = cj & 1;
    const int cbg = cb >> 3, cbi = cb & 7;
    const int jglob = jbase + cj;
    const float br = bhh[jglob], bz = bhh[HH + jglob], bn = bhh[2 * HH + jglob];
    const int ccol = ((cjg * 8 + cbg) + cbi * 8) & 31;
    const int cfl  = (cbi * 32 + ccol) * 2 + cpar;  // float offset inside a [w][g] tile

    // zero own slice of h_0 (ring slot 0), then publish flag = 1
    for (int i = tid; i < JPB * BB; i += THR)
        __stcg(&g_h[0][jbase * BB + i], 0.f);
    __threadfence();
    __syncthreads();
    if (tid == 0) strel(&g_flags[blockIdx.x * 32], 1u);

    const uint64_t zz = dup2(0.f);
    const int kb = w * 64;
    const unsigned* pflag = &g_flags[(8 * w + (lane & 7)) * 32];  // producer flag (lane<8)

    for (int t = 0; t < TT; t++) {
        const float* hin  = g_h[t & 3];
        float*       hout = g_h[(t + 1) & 3];

        // gate-operand prefetch (own slice / static gx: no cross-block dependency)
        const float* gxt = g_gx + (size_t)t * GG * BB;
        float xr = __ldcg(&gxt[(0 * HH + jglob) * BB + cb]);
        float xz = __ldcg(&gxt[(1 * HH + jglob) * BB + cb]);
        float xn = __ldcg(&gxt[(2 * HH + jglob) * BB + cb]);
        float hp = __ldcg(&hin[jglob * BB + cb]);   // own block produced this

        // wait for the 8 producers of this warp's k-range to publish h_t
        if (lane < 8) {
            while (ldacq(pflag) < (unsigned)(t + 1)) { }
        }
        __syncwarp();

        uint64_t aR[8], aZ[8], aN[8];
#pragma unroll
        for (int b = 0; b < 8; b++) { aR[b] = zz; aZ[b] = zz; aN[b] = zz; }

        // ---- k-loop: h straight from L2, weights from smem ----
        const float* hk = hin + (size_t)kb * BB + bg * 8;
#pragma unroll 4
        for (int k2 = 0; k2 < 64; k2++) {
            const int k = kb + k2;
            float4 ha = __ldcg((const float4*)(hk + k2 * BB));
            float4 hc = __ldcg((const float4*)(hk + k2 * BB + 4));
            uint64_t wr  = *(const uint64_t*)&Wsm[(0 * HH + k) * 8 + jg * 2];
            uint64_t wz2 = *(const uint64_t*)&Wsm[(1 * HH + k) * 8 + jg * 2];
            uint64_t wn2 = *(const uint64_t*)&Wsm[(2 * HH + k) * 8 + jg * 2];
            uint64_t d0 = dup2(ha.x), d1 = dup2(ha.y), d2 = dup2(ha.z), d3 = dup2(ha.w);
            uint64_t d4 = dup2(hc.x), d5 = dup2(hc.y), d6 = dup2(hc.z), d7 = dup2(hc.w);
            fma2(aR[0], wr, d0);  fma2(aR[1], wr, d1);  fma2(aR[2], wr, d2);  fma2(aR[3], wr, d3);
            fma2(aR[4], wr, d4);  fma2(aR[5], wr, d5);  fma2(aR[6], wr, d6);  fma2(aR[7], wr, d7);
            fma2(aZ[0], wz2, d0); fma2(aZ[1], wz2, d1); fma2(aZ[2], wz2, d2); fma2(aZ[3], wz2, d3);
            fma2(aZ[4], wz2, d4); fma2(aZ[5], wz2, d5); fma2(aZ[6], wz2, d6); fma2(aZ[7], wz2, d7);
            fma2(aN[0], wn2, d0); fma2(aN[1], wn2, d1); fma2(aN[2], wn2, d2); fma2(aN[3], wn2, d3);
            fma2(aN[4], wn2, d4); fma2(aN[5], wn2, d5); fma2(aN[6], wn2, d6); fma2(aN[7], wn2, d7);
        }

        // ---- store partials ----
#pragma unroll
        for (int bi = 0; bi < 8; bi++) {
            int col = ((jg * 8 + bg) + bi * 8) & 31;
            part[(w * 3 + 0) * 256 + bi * 32 + col] = aR[bi];
            part[(w * 3 + 1) * 256 + bi * 32 + col] = aZ[bi];
            part[(w * 3 + 2) * 256 + bi * 32 + col] = aN[bi];
        }

        // writer gate: h_{t+1} overwrites h_{t-3}; need all blocks past step t-3.
        // Steady-state no-op (skew <= 3 is impossible without this being true).
        if (t >= 3 && tid < NB) {
            const unsigned* fp = &g_flags[tid * 32];
            while (ldacq(fp) < (unsigned)(t - 1)) { }
        }
        __syncthreads();

        // ---- consume: 16-way reduction + gates, one (j,b) per thread ----
        {
            const float* pf = (const float*)part;
            float sR = 0.f, sZ = 0.f, sN = 0.f;
#pragma unroll
            for (int s = 0; s < 16; s++) {
                sR += pf[s * 1536 + 0 * 512 + cfl];
                sZ += pf[s * 1536 + 1 * 512 + cfl];
                sN += pf[s * 1536 + 2 * 512 + cfl];
            }
            float r = sigf(xr + sR + br);
            float z = sigf(xz + sZ + bz);
            float n = tanhf(xn + r * (sN + bn));
            __stcg(&hout[jglob * BB + cb], (1.f - z) * n + z * hp);
        }

        __threadfence();
        __syncthreads();   // all h stores done + part reads done before next step
        if (tid == 0) strel(&g_flags[blockIdx.x * 32], (unsigned)(t + 2));
    }
}

// ---------------- kernel C: FC ----------------
__global__ void k_fc(const float* __restrict__ Wfc, const float* __restrict__ bfc,
                     float* __restrict__ out) {
    int tid = threadIdx.x;
    if (tid >= BB * OO) return;
    int b = tid & 63, o = tid >> 6;
    const float* h = g_h[0];   // h_512 lives in ring slot 512 & 3 = 0
    float a0 = 0.f, a1 = 0.f, a2 = 0.f, a3 = 0.f;
    for (int j = 0; j < HH; j += 4) {
        a0 += h[(j + 0) * BB + b] * Wfc[o * HH + j + 0];
        a1 += h[(j + 1) * BB + b] * Wfc[o * HH + j + 1];
        a2 += h[(j + 2) * BB + b] * Wfc[o * HH + j + 2];
        a3 += h[(j + 3) * BB + b] * Wfc[o * HH + j + 3];
    }
    out[b * OO + o] = a0 + a1 + a2 + a3 + bfc[o];
}

// ---------------- entry ----------------
extern "C" void kernel_launch(void* const* d_in, const int* in_sizes, int n_in,
                              void* d_out, int out_size) {
    const int*   x   = (const int*)d_in[0];
    const float* emb = (const float*)d_in[1];
    const float* Wih = (const float*)d_in[2];
    const float* Whh = (const float*)d_in[3];
    const float* bih = (const float*)d_in[4];
    const float* bhh = (const float*)d_in[5];
    const float* Wfc = (const float*)d_in[6];
    const float* bfc = (const float*)d_in[7];
    float* out = (float*)d_out;

    const int smemA = 2 * EE * BB * (int)sizeof(float);          // 153.6 KB
    const int smemB = (24576 + 24576) * (int)sizeof(float);      // 192 KB
    cudaFuncSetAttribute(k_gx,  cudaFuncAttributeMaxDynamicSharedMemorySize, smemA);
    cudaFuncSetAttribute(k_rnn, cudaFuncAttributeMaxDynamicSharedMemorySize, smemB);

    k_reset<<<1, 128>>>();
    k_transpose<<<(EE * GG + 255) / 256, 256>>>(Wih);
    k_gx<<<TT, 256, smemA>>>(x, emb, bih);
    k_rnn<<<NB, THR, smemB>>>(Whh, bhh);
    k_fc<<<1, 512>>>(Wfc, bfc, out);
}